// round 6
// baseline (speedup 1.0000x reference)
#include <cuda_runtime.h>

#define IMG_H 512
#define IMG_W 512
#define NBATCH 32
#define TILE 64
#define NBLOCKS (8 * 8 * 32)   // 2048

typedef unsigned long long u64;

// Per-block partial sums: .x = n2n sum, .y = weighted wavelet sum.
__device__ double2 g_part[NBLOCKS];
// Monotonic ticket; (old % NBLOCKS == NBLOCKS-1) identifies last block of this launch.
__device__ unsigned int g_ticket = 0;

// ---- f32x2 packed helpers (lane lo = first lane) ----
__device__ __forceinline__ u64 pk(float lo, float hi) {
    u64 r; asm("mov.b64 %0, {%1, %2};" : "=l"(r) : "f"(lo), "f"(hi)); return r;
}
__device__ __forceinline__ float2 upk(u64 v) {
    float2 r; asm("mov.b64 {%0, %1}, %2;" : "=f"(r.x), "=f"(r.y) : "l"(v)); return r;
}
__device__ __forceinline__ u64 f2fma(u64 a, u64 b, u64 c) {
    u64 d; asm("fma.rn.f32x2 %0, %1, %2, %3;" : "=l"(d) : "l"(a), "l"(b), "l"(c)); return d;
}
__device__ __forceinline__ u64 f2mul(u64 a, u64 b) {
    u64 d; asm("mul.rn.f32x2 %0, %1, %2;" : "=l"(d) : "l"(a), "l"(b)); return d;
}

#define K75 0x3F4000003F400000ull   // {0.75, 0.75}
#define K25 0x3E8000003E800000ull   // {0.25, 0.25}
#define KN1 0xBF800000BF800000ull   // {-1.0, -1.0}

__global__ void __launch_bounds__(256, 4) fused_loss_kernel(
    const float* __restrict__ noisy,   // (32,1,512,512)
    const float* __restrict__ weight,  // (1,1,3,3)
    float* __restrict__ out)
{
    const int tx0 = blockIdx.x * TILE;
    const int ty0 = blockIdx.y * TILE;
    const int b   = blockIdx.z;
    const float* img = noisy + (size_t)b * IMG_H * IMG_W;

    __shared__ __align__(16) float sp0[34][36];   // even/even patch (clamped), halo 1
    __shared__ __align__(16) float sp3[34][36];   // odd/odd patch (clamped), halo 1
    __shared__ float sll2[16][17];
    __shared__ double red[2][8];
    __shared__ bool isLast;

    const int t  = threadIdx.x;
    const int k0 = ty0 >> 1;
    const int l0 = tx0 >> 1;

    // conv weights -> packed dups
    u64 w2[9];
    #pragma unroll
    for (int i = 0; i < 9; i++) { float w = __ldg(weight + i); w2[i] = pk(w, w); }

    // ---- load 34x34 p0/p3 patches (index clamp == jax resize edge renorm) ----
    #pragma unroll
    for (int ii = 0; ii < 5; ii++) {
        int idx = t + ii * 256;
        if (idx < 34 * 34) {
            int dy = idx / 34, dx = idx % 34;
            int k = min(max(k0 - 1 + dy, 0), (IMG_H / 2) - 1);
            int l = min(max(l0 - 1 + dx, 0), (IMG_W / 2) - 1);
            sp0[dy][dx] = img[(2 * k) * IMG_W + 2 * l];
            sp3[dy][dx] = img[(2 * k + 1) * IMG_W + 2 * l + 1];
        }
    }
    __syncthreads();

    // ---- per-thread 4x4 output block ----
    const int qqy = t >> 4;                 // 0..15
    const int qqx = t & 15;                 // 0..15
    const int py  = 2 * qqy;                // patch row base
    const int px  = 2 * qqx;                // patch col base
    const int gi_base = ty0 + 4 * qqy - 1;  // fine row of g row 0
    const int gj_base = tx0 + 4 * qqx - 1;  // fine col of g col 0

    const float mc0f = (gj_base >= 0)        ? 1.0f : 0.0f;
    const float mc5f = (gj_base + 5 < IMG_W) ? 1.0f : 0.0f;
    const u64 MC0 = pk(mc0f, mc0f);
    const u64 MC5 = pk(mc5f, mc5f);

    // p0 window 4x4 via float2 LDS
    float P0[4], P1[4], P2[4], P3[4];
    {
        float2 a, c;
        a = *(const float2*)&sp0[py + 0][px]; c = *(const float2*)&sp0[py + 0][px + 2];
        P0[0] = a.x; P0[1] = a.y; P0[2] = c.x; P0[3] = c.y;
        a = *(const float2*)&sp0[py + 1][px]; c = *(const float2*)&sp0[py + 1][px + 2];
        P1[0] = a.x; P1[1] = a.y; P1[2] = c.x; P1[3] = c.y;
        a = *(const float2*)&sp0[py + 2][px]; c = *(const float2*)&sp0[py + 2][px + 2];
        P2[0] = a.x; P2[1] = a.y; P2[2] = c.x; P2[3] = c.y;
        a = *(const float2*)&sp0[py + 3][px]; c = *(const float2*)&sp0[py + 3][px + 2];
        P3[0] = a.x; P3[1] = a.y; P3[2] = c.x; P3[3] = c.y;
    }

    // y-interpolated g1 fine rows 0..5 at the 4 p0 columns (scalar)
    float Y[6][4];
    {
        const float m0 = (gi_base >= 0)        ? 1.0f : 0.0f;
        const float m5 = (gi_base + 5 < IMG_H) ? 1.0f : 0.0f;
        const float wa0 = 0.75f * m0, wb0 = 0.25f * m0;
        const float wa5 = 0.25f * m5, wb5 = 0.75f * m5;
        #pragma unroll
        for (int c = 0; c < 4; c++) {
            Y[0][c] = wa0   * P0[c] + wb0   * P1[c];
            Y[1][c] = 0.25f * P0[c] + 0.75f * P1[c];
            Y[2][c] = 0.75f * P1[c] + 0.25f * P2[c];
            Y[3][c] = 0.25f * P1[c] + 0.75f * P2[c];
            Y[4][c] = 0.75f * P2[c] + 0.25f * P3[c];
            Y[5][c] = wa5   * P2[c] + wb5   * P3[c];
        }
    }

    // Packed g1 fine-row pairs V_j = {g_j, g_{j+1}}, 6 wide, x-interpolated + col-masked.
    #define MAKE_V(V, j) { \
        const u64 Wm0 = pk(Y[j][0], Y[(j) + 1][0]); \
        const u64 Wm1 = pk(Y[j][1], Y[(j) + 1][1]); \
        const u64 Wm2 = pk(Y[j][2], Y[(j) + 1][2]); \
        const u64 Wm3 = pk(Y[j][3], Y[(j) + 1][3]); \
        V[0] = f2mul(f2fma(Wm0, K75, f2mul(Wm1, K25)), MC0); \
        V[1] = f2fma(Wm0, K25, f2mul(Wm1, K75)); \
        V[2] = f2fma(Wm1, K75, f2mul(Wm2, K25)); \
        V[3] = f2fma(Wm1, K25, f2mul(Wm2, K75)); \
        V[4] = f2fma(Wm2, K75, f2mul(Wm3, K25)); \
        V[5] = f2mul(f2fma(Wm2, K25, f2mul(Wm3, K75)), MC5); \
    }

    const float T  = 50.0f / 255.0f;
    const float T4 = T * 0.25f;
    u64 accD1 = 0ull, accD2 = 0ull;   // packed N2N accumulators
    float s1 = 0.0f;
    float ll[2][2];

    u64 V0[6], V1[6], V2[6], V3[6], V4[6];
    MAKE_V(V0, 0) MAKE_V(V1, 1) MAKE_V(V2, 2) MAKE_V(V3, 3) MAKE_V(V4, 4)
    #undef MAKE_V

    // One output row-pair: conv + clamp + g2 + N2N + Haar L1.
    #define DO_PAIR(p, VA, VB, VC) { \
        u64 oc[4]; float o0[4], o1[4]; \
        _Pragma("unroll") \
        for (int ox = 0; ox < 4; ox++) { \
            u64 s = f2mul(VA[ox], w2[0]); \
            s = f2fma(VA[ox + 1], w2[1], s); \
            s = f2fma(VA[ox + 2], w2[2], s); \
            s = f2fma(VB[ox],     w2[3], s); \
            s = f2fma(VB[ox + 1], w2[4], s); \
            s = f2fma(VB[ox + 2], w2[5], s); \
            s = f2fma(VC[ox],     w2[6], s); \
            s = f2fma(VC[ox + 1], w2[7], s); \
            s = f2fma(VC[ox + 2], w2[8], s); \
            float2 v = upk(s); \
            v.x = fminf(fmaxf(v.x, 0.0f), 1.0f); \
            v.y = fminf(fmaxf(v.y, 0.0f), 1.0f); \
            o0[ox] = v.x; o1[ox] = v.y; \
            oc[ox] = pk(v.x, v.y); \
        } \
        /* g2: scalar z rows from p3, then packed column interp */ \
        float zE[4], zO[4]; \
        { \
            float2 a0 = *(const float2*)&sp3[py + (p)    ][px]; \
            float2 b0 = *(const float2*)&sp3[py + (p)    ][px + 2]; \
            float2 a1 = *(const float2*)&sp3[py + (p) + 1][px]; \
            float2 b1 = *(const float2*)&sp3[py + (p) + 1][px + 2]; \
            float2 a2 = *(const float2*)&sp3[py + (p) + 2][px]; \
            float2 b2 = *(const float2*)&sp3[py + (p) + 2][px + 2]; \
            zE[0] = 0.25f * a0.x + 0.75f * a1.x;  zO[0] = 0.75f * a1.x + 0.25f * a2.x; \
            zE[1] = 0.25f * a0.y + 0.75f * a1.y;  zO[1] = 0.75f * a1.y + 0.25f * a2.y; \
            zE[2] = 0.25f * b0.x + 0.75f * b1.x;  zO[2] = 0.75f * b1.x + 0.25f * b2.x; \
            zE[3] = 0.25f * b0.y + 0.75f * b1.y;  zO[3] = 0.75f * b1.y + 0.25f * b2.y; \
        } \
        const u64 Z0 = pk(zE[0], zO[0]), Z1 = pk(zE[1], zO[1]); \
        const u64 Z2 = pk(zE[2], zO[2]), Z3 = pk(zE[3], zO[3]); \
        u64 g2p[4]; \
        g2p[0] = f2fma(Z0, K25, f2mul(Z1, K75)); \
        g2p[1] = f2fma(Z1, K75, f2mul(Z2, K25)); \
        g2p[2] = f2fma(Z1, K25, f2mul(Z2, K75)); \
        g2p[3] = f2fma(Z2, K75, f2mul(Z3, K25)); \
        _Pragma("unroll") \
        for (int ox = 0; ox < 4; ox++) { \
            u64 d1 = f2fma(g2p[ox], KN1, oc[ox]);      /* o - g2 */ \
            accD1 = f2fma(d1, d1, accD1); \
            u64 d2 = f2fma(VB[ox + 1], KN1, oc[ox]);   /* o - g1 (center taps, unmasked lanes) */ \
            accD2 = f2fma(d2, d2, accD2); \
        } \
        _Pragma("unroll") \
        for (int cx = 0; cx < 2; cx++) { \
            const float a = o0[2 * cx], bb = o0[2 * cx + 1]; \
            const float cc = o1[2 * cx], dd = o1[2 * cx + 1]; \
            const float l  = (a + bb + cc + dd) * 0.5f; \
            const float lh = (a - bb + cc - dd) * 0.5f; \
            const float hl = (a + bb - cc - dd) * 0.5f; \
            const float hh = (a - bb - cc + dd) * 0.5f; \
            s1 += fminf(fabsf(lh), T4) + fminf(fabsf(hl), T4) + fminf(fabsf(hh), T4); \
            ll[p][cx] = l; \
        } \
    }

    DO_PAIR(0, V0, V1, V2)
    DO_PAIR(1, V2, V3, V4)
    #undef DO_PAIR

    // fold packed N2N accumulators: rec + 2*reg
    float accA;
    {
        float2 A1 = upk(accD1), A2 = upk(accD2);
        accA = (A1.x + A1.y) + 2.0f * (A2.x + A2.y);
    }

    // ---- Haar level 2 in registers (thread's 4x4 block = one L2 cell) ----
    float s2;
    {
        const float a = ll[0][0], bb = ll[0][1], cc = ll[1][0], dd = ll[1][1];
        const float l  = (a + bb + cc + dd) * 0.5f;
        const float lh = (a - bb + cc - dd) * 0.5f;
        const float hl = (a + bb - cc - dd) * 0.5f;
        const float hh = (a - bb - cc + dd) * 0.5f;
        const float thr = T * 0.5f;
        s2 = fminf(fabsf(lh), thr) + fminf(fabsf(hl), thr) + fminf(fabsf(hh), thr);
        sll2[qqy][qqx] = l;
    }
    __syncthreads();

    // ---- Haar level 3: 8x8 outputs ----
    float s3 = 0.0f;
    if (t < 64) {
        const int r = t >> 3, c = t & 7;
        const float a  = sll2[2 * r][2 * c],     bb = sll2[2 * r][2 * c + 1];
        const float cc = sll2[2 * r + 1][2 * c], dd = sll2[2 * r + 1][2 * c + 1];
        const float lh = (a - bb + cc - dd) * 0.5f;
        const float hl = (a + bb - cc - dd) * 0.5f;
        const float hh = (a - bb - cc + dd) * 0.5f;
        s3 = fminf(fabsf(lh), T) + fminf(fabsf(hl), T) + fminf(fabsf(hh), T);
    }

    // wavelet per-element weights: w_j / (3 * N_j)
    const float c1 = (float)((1.0 / 3.0) / (3.0 * 2097152.0));
    const float c2 = (float)((1.0 / 2.0) / (3.0 * 524288.0));
    const float c3 = (float)(1.0 / (3.0 * 131072.0));
    float mW = c1 * s1 + c2 * s2 + c3 * s3;
    float mA = accA;

    // ---- block reduction ----
    #pragma unroll
    for (int off = 16; off > 0; off >>= 1) {
        mA += __shfl_down_sync(0xffffffff, mA, off);
        mW += __shfl_down_sync(0xffffffff, mW, off);
    }
    const int warp = t >> 5, lane = t & 31;
    if (lane == 0) { red[0][warp] = (double)mA; red[1][warp] = (double)mW; }
    __syncthreads();
    if (t == 0) {
        double A = 0.0, Wv = 0.0;
        #pragma unroll
        for (int i = 0; i < 8; i++) { A += red[0][i]; Wv += red[1][i]; }
        const int bid = (blockIdx.z * gridDim.y + blockIdx.y) * gridDim.x + blockIdx.x;
        g_part[bid] = make_double2(A, Wv);
        __threadfence();
        const unsigned int old = atomicAdd(&g_ticket, 1u);
        isLast = ((old % NBLOCKS) == (NBLOCKS - 1));
    }
    __syncthreads();

    // ---- last block reduces all partials and writes the scalar ----
    if (isLast) {
        double A = 0.0, Wv = 0.0;
        #pragma unroll
        for (int i = t; i < NBLOCKS; i += 256) {
            const double2 p = g_part[i];
            A += p.x; Wv += p.y;
        }
        #pragma unroll
        for (int off = 16; off > 0; off >>= 1) {
            A  += __shfl_down_sync(0xffffffff, A, off);
            Wv += __shfl_down_sync(0xffffffff, Wv, off);
        }
        if (lane == 0) { red[0][warp] = A; red[1][warp] = Wv; }
        __syncthreads();
        if (t == 0) {
            A = 0.0; Wv = 0.0;
            #pragma unroll
            for (int i = 0; i < 8; i++) { A += red[0][i]; Wv += red[1][i]; }
            out[0] = (float)(A / 8388608.0 + 0.05 * Wv);
        }
    }
}

extern "C" void kernel_launch(void* const* d_in, const int* in_sizes, int n_in,
                              void* d_out, int out_size) {
    const float* noisy  = (const float*)d_in[0];
    const float* weight = (const float*)d_in[1];
    float* out = (float*)d_out;

    dim3 grid(IMG_W / TILE, IMG_H / TILE, NBATCH);   // 8 x 8 x 32
    fused_loss_kernel<<<grid, 256>>>(noisy, weight, out);
}

// round 7
// speedup vs baseline: 1.0879x; 1.0879x over previous
#include <cuda_runtime.h>

#define IMG_H 512
#define IMG_W 512
#define NBATCH 32
#define TILE 64
#define NBLOCKS (8 * 8 * 32)   // 2048

typedef unsigned long long u64;

// Per-block partial sums: .x = n2n sum, .y = weighted wavelet sum.
__device__ double2 g_part[NBLOCKS];
// Monotonic ticket; (old % NBLOCKS == NBLOCKS-1) identifies last block of this launch.
__device__ unsigned int g_ticket = 0;

// ---- f32x2 packed helpers (lane lo = first lane) ----
__device__ __forceinline__ u64 pk(float lo, float hi) {
    u64 r; asm("mov.b64 %0, {%1, %2};" : "=l"(r) : "f"(lo), "f"(hi)); return r;
}
__device__ __forceinline__ float2 upk(u64 v) {
    float2 r; asm("mov.b64 {%0, %1}, %2;" : "=f"(r.x), "=f"(r.y) : "l"(v)); return r;
}
__device__ __forceinline__ u64 f2fma(u64 a, u64 b, u64 c) {
    u64 d; asm("fma.rn.f32x2 %0, %1, %2, %3;" : "=l"(d) : "l"(a), "l"(b), "l"(c)); return d;
}
__device__ __forceinline__ u64 f2mul(u64 a, u64 b) {
    u64 d; asm("mul.rn.f32x2 %0, %1, %2;" : "=l"(d) : "l"(a), "l"(b)); return d;
}

#define K75 0x3F4000003F400000ull   // {0.75, 0.75}
#define K25 0x3E8000003E800000ull   // {0.25, 0.25}
#define KN1 0xBF800000BF800000ull   // {-1.0, -1.0}

__global__ void __launch_bounds__(256, 5) fused_loss_kernel(
    const float* __restrict__ noisy,   // (32,1,512,512)
    const float* __restrict__ weight,  // (1,1,3,3)
    float* __restrict__ out)
{
    const int tx0 = blockIdx.x * TILE;
    const int ty0 = blockIdx.y * TILE;
    const int b   = blockIdx.z;
    const float* img = noisy + (size_t)b * IMG_H * IMG_W;

    __shared__ __align__(16) float sp0[34][36];   // even/even patch (clamped), halo 1
    __shared__ __align__(16) float sp3[34][36];   // odd/odd patch (clamped), halo 1
    __shared__ float sll2[16][17];
    __shared__ double red[2][8];
    __shared__ bool isLast;

    const int t  = threadIdx.x;
    const int k0 = ty0 >> 1;
    const int l0 = tx0 >> 1;

    // conv weights -> packed dups
    u64 w2[9];
    #pragma unroll
    for (int i = 0; i < 9; i++) { float w = __ldg(weight + i); w2[i] = pk(w, w); }

    // ---- load 34x34 p0/p3 patches (index clamp == jax resize edge renorm) ----
    #pragma unroll
    for (int ii = 0; ii < 5; ii++) {
        int idx = t + ii * 256;
        if (idx < 34 * 34) {
            int dy = idx / 34, dx = idx % 34;
            int k = min(max(k0 - 1 + dy, 0), (IMG_H / 2) - 1);
            int l = min(max(l0 - 1 + dx, 0), (IMG_W / 2) - 1);
            sp0[dy][dx] = img[(2 * k) * IMG_W + 2 * l];
            sp3[dy][dx] = img[(2 * k + 1) * IMG_W + 2 * l + 1];
        }
    }
    __syncthreads();

    // ---- per-thread 4x4 output block ----
    const int qqy = t >> 4;                 // 0..15
    const int qqx = t & 15;                 // 0..15
    const int py  = 2 * qqy;                // patch row base
    const int px  = 2 * qqx;                // patch col base
    const int gi_base = ty0 + 4 * qqy - 1;  // fine row of g row 0
    const int gj_base = tx0 + 4 * qqx - 1;  // fine col of g col 0

    const float mc0f = (gj_base >= 0)        ? 1.0f : 0.0f;
    const float mc5f = (gj_base + 5 < IMG_W) ? 1.0f : 0.0f;
    const u64 MC0 = pk(mc0f, mc0f);
    const u64 MC5 = pk(mc5f, mc5f);

    // Build scalar y-interpolated g1 fine row r (r compile-time) into dst[4].
    #define Y_ROW(dst, r) { \
        const int pr = (r) >> 1; \
        float wa = ((r) & 1) ? 0.25f : 0.75f; \
        float m = 1.0f; \
        if ((r) == 0) m = (gi_base >= 0)        ? 1.0f : 0.0f; \
        if ((r) == 5) m = (gi_base + 5 < IMG_H) ? 1.0f : 0.0f; \
        wa *= m; const float wb = m - wa; \
        const float2 a  = *(const float2*)&sp0[py + pr][px]; \
        const float2 c  = *(const float2*)&sp0[py + pr][px + 2]; \
        const float2 a2 = *(const float2*)&sp0[py + pr + 1][px]; \
        const float2 c2 = *(const float2*)&sp0[py + pr + 1][px + 2]; \
        dst[0] = wa * a.x + wb * a2.x; \
        dst[1] = wa * a.y + wb * a2.y; \
        dst[2] = wa * c.x + wb * c2.x; \
        dst[3] = wa * c.y + wb * c2.y; \
    }

    // Pack two scalar fine rows into a 6-wide x-interpolated, col-masked row-pair.
    #define MAKE_V(V, ylo, yhi) { \
        const u64 Wm0 = pk(ylo[0], yhi[0]); \
        const u64 Wm1 = pk(ylo[1], yhi[1]); \
        const u64 Wm2 = pk(ylo[2], yhi[2]); \
        const u64 Wm3 = pk(ylo[3], yhi[3]); \
        V[0] = f2mul(f2fma(Wm0, K75, f2mul(Wm1, K25)), MC0); \
        V[1] = f2fma(Wm0, K25, f2mul(Wm1, K75)); \
        V[2] = f2fma(Wm1, K75, f2mul(Wm2, K25)); \
        V[3] = f2fma(Wm1, K25, f2mul(Wm2, K75)); \
        V[4] = f2fma(Wm2, K75, f2mul(Wm3, K25)); \
        V[5] = f2mul(f2fma(Wm2, K25, f2mul(Wm3, K75)), MC5); \
    }

    const float T  = 50.0f / 255.0f;
    const float T4 = T * 0.25f;
    u64 accD1 = 0ull, accD2 = 0ull;
    float s1 = 0.0f;
    float ll[2][2];

    // One output row-pair: conv + clamp + g2 + N2N + Haar L1.
    #define DO_PAIR(p, VA, VB, VC) { \
        u64 oc[4]; float o0[4], o1[4]; \
        _Pragma("unroll") \
        for (int ox = 0; ox < 4; ox++) { \
            u64 s = f2mul(VA[ox], w2[0]); \
            s = f2fma(VA[ox + 1], w2[1], s); \
            s = f2fma(VA[ox + 2], w2[2], s); \
            s = f2fma(VB[ox],     w2[3], s); \
            s = f2fma(VB[ox + 1], w2[4], s); \
            s = f2fma(VB[ox + 2], w2[5], s); \
            s = f2fma(VC[ox],     w2[6], s); \
            s = f2fma(VC[ox + 1], w2[7], s); \
            s = f2fma(VC[ox + 2], w2[8], s); \
            float2 v = upk(s); \
            v.x = fminf(fmaxf(v.x, 0.0f), 1.0f); \
            v.y = fminf(fmaxf(v.y, 0.0f), 1.0f); \
            o0[ox] = v.x; o1[ox] = v.y; \
            oc[ox] = pk(v.x, v.y); \
        } \
        float zE[4], zO[4]; \
        { \
            const float2 a0 = *(const float2*)&sp3[py + (p)    ][px]; \
            const float2 b0 = *(const float2*)&sp3[py + (p)    ][px + 2]; \
            const float2 a1 = *(const float2*)&sp3[py + (p) + 1][px]; \
            const float2 b1 = *(const float2*)&sp3[py + (p) + 1][px + 2]; \
            const float2 a2 = *(const float2*)&sp3[py + (p) + 2][px]; \
            const float2 b2 = *(const float2*)&sp3[py + (p) + 2][px + 2]; \
            zE[0] = 0.25f * a0.x + 0.75f * a1.x;  zO[0] = 0.75f * a1.x + 0.25f * a2.x; \
            zE[1] = 0.25f * a0.y + 0.75f * a1.y;  zO[1] = 0.75f * a1.y + 0.25f * a2.y; \
            zE[2] = 0.25f * b0.x + 0.75f * b1.x;  zO[2] = 0.75f * b1.x + 0.25f * b2.x; \
            zE[3] = 0.25f * b0.y + 0.75f * b1.y;  zO[3] = 0.75f * b1.y + 0.25f * b2.y; \
        } \
        const u64 Z0 = pk(zE[0], zO[0]), Z1 = pk(zE[1], zO[1]); \
        const u64 Z2 = pk(zE[2], zO[2]), Z3 = pk(zE[3], zO[3]); \
        u64 g2p[4]; \
        g2p[0] = f2fma(Z0, K25, f2mul(Z1, K75)); \
        g2p[1] = f2fma(Z1, K75, f2mul(Z2, K25)); \
        g2p[2] = f2fma(Z1, K25, f2mul(Z2, K75)); \
        g2p[3] = f2fma(Z2, K75, f2mul(Z3, K25)); \
        _Pragma("unroll") \
        for (int ox = 0; ox < 4; ox++) { \
            u64 d1 = f2fma(g2p[ox], KN1, oc[ox]); \
            accD1 = f2fma(d1, d1, accD1); \
            u64 d2 = f2fma(VB[ox + 1], KN1, oc[ox]); \
            accD2 = f2fma(d2, d2, accD2); \
        } \
        _Pragma("unroll") \
        for (int cx = 0; cx < 2; cx++) { \
            const float a  = o0[2 * cx], bb = o0[2 * cx + 1]; \
            const float cc = o1[2 * cx], dd = o1[2 * cx + 1]; \
            const float l  = (a + bb + cc + dd) * 0.5f; \
            const float lh = (a - bb + cc - dd) * 0.5f; \
            const float hl = (a + bb - cc - dd) * 0.5f; \
            const float hh = (a - bb - cc + dd) * 0.5f; \
            s1 += fminf(fabsf(lh), T4) + fminf(fabsf(hl), T4) + fminf(fabsf(hh), T4); \
            ll[p][cx] = l; \
        } \
    }

    // ---- pair-sequential pipeline (peak live V-state: 3 row-pairs) ----
    {
        u64 VA[6], VB[6], VC[6];
        float ya[4], yb[4], yc[4], yd[4];

        // pair 0: fine rows f0..f3
        Y_ROW(ya, 0) Y_ROW(yb, 1) Y_ROW(yc, 2) Y_ROW(yd, 3)
        MAKE_V(VA, ya, yb)
        MAKE_V(VB, yb, yc)
        MAKE_V(VC, yc, yd)
        DO_PAIR(0, VA, VB, VC)

        // pair 1: fine rows f2..f5 ; reuse VC as its VA, rebuild VA<-V3, VB<-V4
        Y_ROW(ya, 4) Y_ROW(yb, 5)
        MAKE_V(VA, yd, ya)   // V3 = {f3, f4}
        MAKE_V(VB, ya, yb)   // V4 = {f4, f5}
        DO_PAIR(1, VC, VA, VB)
    }
    #undef Y_ROW
    #undef MAKE_V
    #undef DO_PAIR

    // fold packed N2N accumulators: rec + 2*reg
    float accA;
    {
        const float2 A1 = upk(accD1), A2 = upk(accD2);
        accA = (A1.x + A1.y) + 2.0f * (A2.x + A2.y);
    }

    // ---- Haar level 2 in registers (thread's 4x4 block = one L2 cell) ----
    float s2;
    {
        const float a = ll[0][0], bb = ll[0][1], cc = ll[1][0], dd = ll[1][1];
        const float l  = (a + bb + cc + dd) * 0.5f;
        const float lh = (a - bb + cc - dd) * 0.5f;
        const float hl = (a + bb - cc - dd) * 0.5f;
        const float hh = (a - bb - cc + dd) * 0.5f;
        const float thr = T * 0.5f;
        s2 = fminf(fabsf(lh), thr) + fminf(fabsf(hl), thr) + fminf(fabsf(hh), thr);
        sll2[qqy][qqx] = l;
    }
    __syncthreads();

    // ---- Haar level 3: 8x8 outputs ----
    float s3 = 0.0f;
    if (t < 64) {
        const int r = t >> 3, c = t & 7;
        const float a  = sll2[2 * r][2 * c],     bb = sll2[2 * r][2 * c + 1];
        const float cc = sll2[2 * r + 1][2 * c], dd = sll2[2 * r + 1][2 * c + 1];
        const float lh = (a - bb + cc - dd) * 0.5f;
        const float hl = (a + bb - cc - dd) * 0.5f;
        const float hh = (a - bb - cc + dd) * 0.5f;
        s3 = fminf(fabsf(lh), T) + fminf(fabsf(hl), T) + fminf(fabsf(hh), T);
    }

    // wavelet per-element weights: w_j / (3 * N_j)
    const float c1 = (float)((1.0 / 3.0) / (3.0 * 2097152.0));
    const float c2 = (float)((1.0 / 2.0) / (3.0 * 524288.0));
    const float c3 = (float)(1.0 / (3.0 * 131072.0));
    float mW = c1 * s1 + c2 * s2 + c3 * s3;
    float mA = accA;

    // ---- block reduction ----
    #pragma unroll
    for (int off = 16; off > 0; off >>= 1) {
        mA += __shfl_down_sync(0xffffffff, mA, off);
        mW += __shfl_down_sync(0xffffffff, mW, off);
    }
    const int warp = t >> 5, lane = t & 31;
    if (lane == 0) { red[0][warp] = (double)mA; red[1][warp] = (double)mW; }
    __syncthreads();
    if (t == 0) {
        double A = 0.0, Wv = 0.0;
        #pragma unroll
        for (int i = 0; i < 8; i++) { A += red[0][i]; Wv += red[1][i]; }
        const int bid = (blockIdx.z * gridDim.y + blockIdx.y) * gridDim.x + blockIdx.x;
        g_part[bid] = make_double2(A, Wv);
        __threadfence();
        const unsigned int old = atomicAdd(&g_ticket, 1u);
        isLast = ((old % NBLOCKS) == (NBLOCKS - 1));
    }
    __syncthreads();

    // ---- last block reduces all partials and writes the scalar ----
    if (isLast) {
        double A = 0.0, Wv = 0.0;
        #pragma unroll
        for (int i = t; i < NBLOCKS; i += 256) {
            const double2 p = g_part[i];
            A += p.x; Wv += p.y;
        }
        #pragma unroll
        for (int off = 16; off > 0; off >>= 1) {
            A  += __shfl_down_sync(0xffffffff, A, off);
            Wv += __shfl_down_sync(0xffffffff, Wv, off);
        }
        if (lane == 0) { red[0][warp] = A; red[1][warp] = Wv; }
        __syncthreads();
        if (t == 0) {
            A = 0.0; Wv = 0.0;
            #pragma unroll
            for (int i = 0; i < 8; i++) { A += red[0][i]; Wv += red[1][i]; }
            out[0] = (float)(A / 8388608.0 + 0.05 * Wv);
        }
    }
}

extern "C" void kernel_launch(void* const* d_in, const int* in_sizes, int n_in,
                              void* d_out, int out_size) {
    const float* noisy  = (const float*)d_in[0];
    const float* weight = (const float*)d_in[1];
    float* out = (float*)d_out;

    dim3 grid(IMG_W / TILE, IMG_H / TILE, NBATCH);   // 8 x 8 x 32
    fused_loss_kernel<<<grid, 256>>>(noisy, weight, out);
}

// round 10
// speedup vs baseline: 1.1000x; 1.0111x over previous
#include <cuda_runtime.h>

#define IMG_H 512
#define IMG_W 512
#define NBATCH 32
#define TILE 64
#define NBLOCKS (8 * 8 * 32)   // 2048

typedef unsigned long long u64;

// Per-block partial sums: .x = n2n sum, .y = weighted wavelet sum.
__device__ double2 g_part[NBLOCKS];
// Monotonic ticket; (old % NBLOCKS == NBLOCKS-1) identifies last block of this launch.
__device__ unsigned int g_ticket = 0;

// ---- f32x2 packed helpers ----
__device__ __forceinline__ u64 pk(float lo, float hi) {
    u64 r; asm("mov.b64 %0, {%1, %2};" : "=l"(r) : "f"(lo), "f"(hi)); return r;
}
__device__ __forceinline__ float2 upk(u64 v) {
    float2 r; asm("mov.b64 {%0, %1}, %2;" : "=f"(r.x), "=f"(r.y) : "l"(v)); return r;
}
__device__ __forceinline__ u64 f2fma(u64 a, u64 b, u64 c) {
    u64 d; asm("fma.rn.f32x2 %0, %1, %2, %3;" : "=l"(d) : "l"(a), "l"(b), "l"(c)); return d;
}
__device__ __forceinline__ u64 f2mul(u64 a, u64 b) {
    u64 d; asm("mul.rn.f32x2 %0, %1, %2;" : "=l"(d) : "l"(a), "l"(b)); return d;
}

#define K75 0x3F4000003F400000ull   // {0.75, 0.75}
#define K25 0x3E8000003E800000ull   // {0.25, 0.25}
#define KN1 0xBF800000BF800000ull   // {-1.0, -1.0}

__global__ void __launch_bounds__(256, 6) fused_loss_kernel(
    const float* __restrict__ noisy,   // (32,1,512,512)
    const float* __restrict__ weight,  // (1,1,3,3)
    float* __restrict__ out)
{
    const int tx0 = blockIdx.x * TILE;
    const int ty0 = blockIdx.y * TILE;
    const int b   = blockIdx.z;
    const float* img = noisy + (size_t)b * IMG_H * IMG_W;

    __shared__ __align__(16) float sp0[34][36];   // even/even patch (clamped), halo 1
    __shared__ __align__(16) float sp3[34][36];   // odd/odd patch (clamped), halo 1
    __shared__ float sll2[16][17];
    __shared__ double red[2][8];
    __shared__ bool isLast;

    const int t  = threadIdx.x;
    const int k0 = ty0 >> 1;
    const int l0 = tx0 >> 1;

    // conv weights -> packed dups
    u64 w2[9];
    #pragma unroll
    for (int i = 0; i < 9; i++) { float w = __ldg(weight + i); w2[i] = pk(w, w); }

    // ---- load 34x34 p0/p3 patches (index clamp == jax resize edge renorm) ----
    #pragma unroll
    for (int ii = 0; ii < 5; ii++) {
        int idx = t + ii * 256;
        if (idx < 34 * 34) {
            int dy = idx / 34, dx = idx % 34;
            int k = min(max(k0 - 1 + dy, 0), (IMG_H / 2) - 1);
            int l = min(max(l0 - 1 + dx, 0), (IMG_W / 2) - 1);
            sp0[dy][dx] = img[(2 * k) * IMG_W + 2 * l];
            sp3[dy][dx] = img[(2 * k + 1) * IMG_W + 2 * l + 1];
        }
    }
    __syncthreads();

    // ---- per-thread 4x4 output block ----
    const int qqy = t >> 4;                 // 0..15
    const int qqx = t & 15;                 // 0..15
    const int py  = 2 * qqy;                // patch row base
    const int px  = 2 * qqx;                // patch col base
    const int gi_base = ty0 + 4 * qqy - 1;  // fine row of g row 0
    const int gj_base = tx0 + 4 * qqx - 1;  // fine col of g col 0

    const float mc0f = (gj_base >= 0)        ? 1.0f : 0.0f;
    const float mc5f = (gj_base + 5 < IMG_W) ? 1.0f : 0.0f;
    const u64 MC0 = pk(mc0f, mc0f);
    const u64 MC5 = pk(mc5f, mc5f);

    // load p0 patch row r (4 floats) into P
    #define LOAD_P(P, r) { \
        const float2 _a = *(const float2*)&sp0[py + (r)][px]; \
        const float2 _b = *(const float2*)&sp0[py + (r)][px + 2]; \
        P[0] = _a.x; P[1] = _a.y; P[2] = _b.x; P[3] = _b.y; }

    // y-interp: dst = wa*Pl + wb*Ph (4 wide)
    #define YMIX(dst, Pl, Ph, wa, wb) { \
        dst[0] = (wa) * Pl[0] + (wb) * Ph[0]; \
        dst[1] = (wa) * Pl[1] + (wb) * Ph[1]; \
        dst[2] = (wa) * Pl[2] + (wb) * Ph[2]; \
        dst[3] = (wa) * Pl[3] + (wb) * Ph[3]; }

    // pack two fine rows -> 6-wide x-interpolated, col-masked packed row-pair
    #define MAKE_V(V, ylo, yhi) { \
        const u64 Wm0 = pk(ylo[0], yhi[0]); \
        const u64 Wm1 = pk(ylo[1], yhi[1]); \
        const u64 Wm2 = pk(ylo[2], yhi[2]); \
        const u64 Wm3 = pk(ylo[3], yhi[3]); \
        V[0] = f2mul(f2fma(Wm0, K75, f2mul(Wm1, K25)), MC0); \
        V[1] = f2fma(Wm0, K25, f2mul(Wm1, K75)); \
        V[2] = f2fma(Wm1, K75, f2mul(Wm2, K25)); \
        V[3] = f2fma(Wm1, K25, f2mul(Wm2, K75)); \
        V[4] = f2fma(Wm2, K75, f2mul(Wm3, K25)); \
        V[5] = f2mul(f2fma(Wm2, K25, f2mul(Wm3, K75)), MC5); \
    }

    #define CONV_FIRST(S, V, wi) { \
        _Pragma("unroll") \
        for (int ox = 0; ox < 4; ox++) { \
            S[ox] = f2mul(V[ox], w2[wi]); \
            S[ox] = f2fma(V[ox + 1], w2[(wi) + 1], S[ox]); \
            S[ox] = f2fma(V[ox + 2], w2[(wi) + 2], S[ox]); \
        } }

    #define CONV_ROW(S, V, wi) { \
        _Pragma("unroll") \
        for (int ox = 0; ox < 4; ox++) { \
            S[ox] = f2fma(V[ox],     w2[wi],       S[ox]); \
            S[ox] = f2fma(V[ox + 1], w2[(wi) + 1], S[ox]); \
            S[ox] = f2fma(V[ox + 2], w2[(wi) + 2], S[ox]); \
        } }

    const float T  = 50.0f / 255.0f;
    const float T4 = T * 0.25f;
    u64 accD1 = 0ull, accD2 = 0ull;
    float s1 = 0.0f;
    float ll[2][2];

    // Epilogue of one row-pair: clamp + g2 + N2N + Haar L1. VB = middle row-pair (g1 centers).
    #define PAIR_EPI(p, S, VB) { \
        u64 oc[4]; float o0[4], o1[4]; \
        _Pragma("unroll") \
        for (int ox = 0; ox < 4; ox++) { \
            float2 v = upk(S[ox]); \
            v.x = fminf(fmaxf(v.x, 0.0f), 1.0f); \
            v.y = fminf(fmaxf(v.y, 0.0f), 1.0f); \
            o0[ox] = v.x; o1[ox] = v.y; \
            oc[ox] = pk(v.x, v.y); \
        } \
        float zE[4], zO[4]; \
        { \
            const float2 a0 = *(const float2*)&sp3[py + (p)    ][px]; \
            const float2 b0 = *(const float2*)&sp3[py + (p)    ][px + 2]; \
            const float2 a1 = *(const float2*)&sp3[py + (p) + 1][px]; \
            const float2 b1 = *(const float2*)&sp3[py + (p) + 1][px + 2]; \
            const float2 a2 = *(const float2*)&sp3[py + (p) + 2][px]; \
            const float2 b2 = *(const float2*)&sp3[py + (p) + 2][px + 2]; \
            zE[0] = 0.25f * a0.x + 0.75f * a1.x;  zO[0] = 0.75f * a1.x + 0.25f * a2.x; \
            zE[1] = 0.25f * a0.y + 0.75f * a1.y;  zO[1] = 0.75f * a1.y + 0.25f * a2.y; \
            zE[2] = 0.25f * b0.x + 0.75f * b1.x;  zO[2] = 0.75f * b1.x + 0.25f * b2.x; \
            zE[3] = 0.25f * b0.y + 0.75f * b1.y;  zO[3] = 0.75f * b1.y + 0.25f * b2.y; \
        } \
        const u64 Z0 = pk(zE[0], zO[0]), Z1 = pk(zE[1], zO[1]); \
        const u64 Z2 = pk(zE[2], zO[2]), Z3 = pk(zE[3], zO[3]); \
        u64 g2p[4]; \
        g2p[0] = f2fma(Z0, K25, f2mul(Z1, K75)); \
        g2p[1] = f2fma(Z1, K75, f2mul(Z2, K25)); \
        g2p[2] = f2fma(Z1, K25, f2mul(Z2, K75)); \
        g2p[3] = f2fma(Z2, K75, f2mul(Z3, K25)); \
        _Pragma("unroll") \
        for (int ox = 0; ox < 4; ox++) { \
            u64 d1 = f2fma(g2p[ox], KN1, oc[ox]); \
            accD1 = f2fma(d1, d1, accD1); \
            u64 d2 = f2fma(VB[ox + 1], KN1, oc[ox]); \
            accD2 = f2fma(d2, d2, accD2); \
        } \
        _Pragma("unroll") \
        for (int cx = 0; cx < 2; cx++) { \
            const float a  = o0[2 * cx], bb = o0[2 * cx + 1]; \
            const float cc = o1[2 * cx], dd = o1[2 * cx + 1]; \
            const float l  = (a + bb + cc + dd) * 0.5f; \
            const float lh = (a - bb + cc - dd) * 0.5f; \
            const float hl = (a + bb - cc - dd) * 0.5f; \
            const float hh = (a - bb - cc + dd) * 0.5f; \
            s1 += fminf(fabsf(lh), T4) + fminf(fabsf(hl), T4) + fminf(fabsf(hh), T4); \
            ll[p][cx] = l; \
        } \
    }

    // ---- streaming conv pipeline: build each packed V row, consume immediately ----
    {
        const float m0 = (gi_base >= 0)        ? 1.0f : 0.0f;
        const float m5 = (gi_base + 5 < IMG_H) ? 1.0f : 0.0f;

        float Pa[4], Pb[4];          // rolling p0 rows
        float y0[4], y1[4];          // rolling fine rows
        u64 V[6], Vk[6], S[4];

        // --- pair 0 (output rows 0,1) ---
        LOAD_P(Pa, 0) LOAD_P(Pb, 1)                  // P0, P1
        YMIX(y0, Pa, Pb, 0.75f * m0, 0.25f * m0)     // f0 (masked)
        YMIX(y1, Pa, Pb, 0.25f, 0.75f)               // f1
        MAKE_V(V, y0, y1)                            // V0 = {f0,f1}
        CONV_FIRST(S, V, 0)

        LOAD_P(Pa, 2)                                // Pa = P2 (P0 dead)
        YMIX(y0, Pb, Pa, 0.75f, 0.25f)               // f2
        MAKE_V(V, y1, y0)                            // V1 = {f1,f2}
        CONV_ROW(S, V, 3)

        YMIX(y1, Pb, Pa, 0.25f, 0.75f)               // f3
        MAKE_V(Vk, y0, y1)                           // V2 = {f2,f3} (lives into pair 1)
        CONV_ROW(S, Vk, 6)

        PAIR_EPI(0, S, V)                            // g1 centers = V1

        // --- pair 1 (output rows 2,3) ---
        CONV_FIRST(S, Vk, 0)                         // row A = V2

        LOAD_P(Pb, 3)                                // Pb = P3 (P1 dead)
        YMIX(y0, Pa, Pb, 0.75f, 0.25f)               // f4
        MAKE_V(V, y1, y0)                            // V3 = {f3,f4}
        CONV_ROW(S, V, 3)

        YMIX(y1, Pa, Pb, 0.25f * m5, 0.75f * m5)     // f5 (masked)
        MAKE_V(Vk, y0, y1)                           // V4 = {f4,f5}
        CONV_ROW(S, Vk, 6)

        PAIR_EPI(1, S, V)                            // g1 centers = V3
    }
    #undef LOAD_P
    #undef YMIX
    #undef MAKE_V
    #undef CONV_FIRST
    #undef CONV_ROW
    #undef PAIR_EPI

    // fold packed N2N accumulators: rec + 2*reg
    float accA;
    {
        const float2 A1 = upk(accD1), A2 = upk(accD2);
        accA = (A1.x + A1.y) + 2.0f * (A2.x + A2.y);
    }

    // ---- Haar level 2 in registers ----
    float s2;
    {
        const float a = ll[0][0], bb = ll[0][1], cc = ll[1][0], dd = ll[1][1];
        const float l  = (a + bb + cc + dd) * 0.5f;
        const float lh = (a - bb + cc - dd) * 0.5f;
        const float hl = (a + bb - cc - dd) * 0.5f;
        const float hh = (a - bb - cc + dd) * 0.5f;
        const float thr = T * 0.5f;
        s2 = fminf(fabsf(lh), thr) + fminf(fabsf(hl), thr) + fminf(fabsf(hh), thr);
        sll2[qqy][qqx] = l;
    }
    __syncthreads();

    // ---- Haar level 3: 8x8 outputs ----
    float s3 = 0.0f;
    if (t < 64) {
        const int r = t >> 3, c = t & 7;
        const float a  = sll2[2 * r][2 * c],     bb = sll2[2 * r][2 * c + 1];
        const float cc = sll2[2 * r + 1][2 * c], dd = sll2[2 * r + 1][2 * c + 1];
        const float lh = (a - bb + cc - dd) * 0.5f;
        const float hl = (a + bb - cc - dd) * 0.5f;
        const float hh = (a - bb - cc + dd) * 0.5f;
        s3 = fminf(fabsf(lh), T) + fminf(fabsf(hl), T) + fminf(fabsf(hh), T);
    }

    // wavelet per-element weights: w_j / (3 * N_j)
    const float c1 = (float)((1.0 / 3.0) / (3.0 * 2097152.0));
    const float c2 = (float)((1.0 / 2.0) / (3.0 * 524288.0));
    const float c3 = (float)(1.0 / (3.0 * 131072.0));
    float mW = c1 * s1 + c2 * s2 + c3 * s3;
    float mA = accA;

    // ---- block reduction ----
    #pragma unroll
    for (int off = 16; off > 0; off >>= 1) {
        mA += __shfl_down_sync(0xffffffff, mA, off);
        mW += __shfl_down_sync(0xffffffff, mW, off);
    }
    const int warp = t >> 5, lane = t & 31;
    if (lane == 0) { red[0][warp] = (double)mA; red[1][warp] = (double)mW; }
    __syncthreads();
    if (t == 0) {
        double A = 0.0, Wv = 0.0;
        #pragma unroll
        for (int i = 0; i < 8; i++) { A += red[0][i]; Wv += red[1][i]; }
        const int bid = (blockIdx.z * gridDim.y + blockIdx.y) * gridDim.x + blockIdx.x;
        g_part[bid] = make_double2(A, Wv);
        __threadfence();
        const unsigned int old = atomicAdd(&g_ticket, 1u);
        isLast = ((old % NBLOCKS) == (NBLOCKS - 1));
    }
    __syncthreads();

    // ---- last block reduces all partials and writes the scalar ----
    if (isLast) {
        double A = 0.0, Wv = 0.0;
        #pragma unroll
        for (int i = t; i < NBLOCKS; i += 256) {
            const double2 p = g_part[i];
            A += p.x; Wv += p.y;
        }
        #pragma unroll
        for (int off = 16; off > 0; off >>= 1) {
            A  += __shfl_down_sync(0xffffffff, A, off);
            Wv += __shfl_down_sync(0xffffffff, Wv, off);
        }
        if (lane == 0) { red[0][warp] = A; red[1][warp] = Wv; }
        __syncthreads();
        if (t == 0) {
            A = 0.0; Wv = 0.0;
            #pragma unroll
            for (int i = 0; i < 8; i++) { A += red[0][i]; Wv += red[1][i]; }
            out[0] = (float)(A / 8388608.0 + 0.05 * Wv);
        }
    }
}

extern "C" void kernel_launch(void* const* d_in, const int* in_sizes, int n_in,
                              void* d_out, int out_size) {
    const float* noisy  = (const float*)d_in[0];
    const float* weight = (const float*)d_in[1];
    float* out = (float*)d_out;

    dim3 grid(IMG_W / TILE, IMG_H / TILE, NBATCH);   // 8 x 8 x 32
    fused_loss_kernel<<<grid, 256>>>(noisy, weight, out);
}